// round 16
// baseline (speedup 1.0000x reference)
#include <cuda_runtime.h>
#include <cuda_bf16.h>

// Problem constants
#define Hd   256
#define Ld   512
#define Bq   8
#define NTOK 4096            // B*L
#define Vv   32000
#define CEMA 0.05f           // 1 - alpha
#define CSZ  64              // chunk size
#define NCH  8               // chunks per batch
#define KSTR 260             // K-tile smem row stride (scan, fp32 words)
#define TSTR 68              // T smem row stride
#define STRB 264             // prep bf16 key row stride
#define GSTR 40              // gemm bf16 smem row stride (BK=32 + pad)

typedef __nv_bfloat16 bf16;

// Scratch (device globals)
__device__ bf16  g_W1h[512 * Hd],   g_W1l[512 * Hd];
__device__ bf16  g_W2h[Hd * 512],   g_W2l[Hd * 512];
__device__ bf16  g_t1h[NTOK * 512], g_t1l[NTOK * 512];
__device__ bf16  g_Khg[NTOK * Hd],  g_Klg[NTOK * Hd];   // LN'd keys, bf16 hi/lo
__device__ float g_x [NTOK * Hd];
__device__ float g_he[NTOK * Hd];
__device__ float g_in[NTOK];
__device__ float g_T [Bq * NCH * CSZ * CSZ];
__device__ float g_mm[Bq * Hd];

// cp.async helpers
__device__ __forceinline__ void cp16(void* dst, const void* src) {
    unsigned d = (unsigned)__cvta_generic_to_shared(dst);
    asm volatile("cp.async.ca.shared.global [%0], [%1], 16;\n" :: "r"(d), "l"(src));
}
#define CP_COMMIT() asm volatile("cp.async.commit_group;\n" ::: "memory")
#define CP_WAIT(n)  asm volatile("cp.async.wait_group %0;\n" :: "n"(n) : "memory")

__device__ __forceinline__ void mma_bf16(float* d, const unsigned* a, const unsigned* b) {
    asm volatile(
        "mma.sync.aligned.m16n8k16.row.col.f32.bf16.bf16.f32 "
        "{%0,%1,%2,%3}, {%4,%5,%6,%7}, {%8,%9}, {%0,%1,%2,%3};"
        : "+f"(d[0]), "+f"(d[1]), "+f"(d[2]), "+f"(d[3])
        : "r"(a[0]), "r"(a[1]), "r"(a[2]), "r"(a[3]), "r"(b[0]), "r"(b[1]));
}

__device__ __forceinline__ void ldsm4(unsigned* r, unsigned addr) {
    asm volatile("ldmatrix.sync.aligned.m8n8.x4.shared.b16 {%0,%1,%2,%3}, [%4];"
        : "=r"(r[0]), "=r"(r[1]), "=r"(r[2]), "=r"(r[3]) : "r"(addr));
}

__device__ __forceinline__ void split2(float v, bf16& h, bf16& l) {
    h = __float2bfloat16_rn(v);
    l = __float2bfloat16_rn(v - __bfloat162float(h));
}

// ---------------------------------------------------------------------------
// W transpose/split kernels (split so gemm2 lands in profiled slot 4)
// ---------------------------------------------------------------------------
__global__ __launch_bounds__(256) void convW_kernel(
    const float* __restrict__ W, bf16* __restrict__ Wh, bf16* __restrict__ Wl,
    int K, int N, int nBlkX)
{
    __shared__ float tile[32][33];
    const int p = blockIdx.x;
    const int n0 = (p % nBlkX) * 32, k0 = (p / nBlkX) * 32;
    const int tx = threadIdx.x & 31, ty = threadIdx.x >> 5;
    #pragma unroll
    for (int i = 0; i < 4; i++)
        tile[ty + 8 * i][tx] = W[(long)(k0 + ty + 8 * i) * N + n0 + tx];
    __syncthreads();
    #pragma unroll
    for (int i = 0; i < 4; i++) {
        const int row = ty + 8 * i;
        const float v = tile[tx][row];
        bf16 h, l; split2(v, h, l);
        Wh[(long)(n0 + row) * K + k0 + tx] = h;
        Wl[(long)(n0 + row) * K + k0 + tx] = l;
    }
}

// ---------------------------------------------------------------------------
// Tensor-core GEMM (mma.sync HMMA), bf16x3 split, ldmatrix, BK=32,
// 3 blocks/SM. Block 64x128, 8 warps (2x4), warp tile 32x32,
// cp.async double buffer. GATHER: A from fp32 embed[seq] via registers.
// MODE 1: +bias, relu, write bf16 hi/lo. MODE 2: +bias, +embed residual, fp32.
// ---------------------------------------------------------------------------
template<int MODE, bool GATHER>
__global__ __launch_bounds__(256, 3) void mma_gemm_kernel(
    const bf16* __restrict__ Agh, const bf16* __restrict__ Agl,
    const bf16* __restrict__ Bgh, const bf16* __restrict__ Bgl,
    const float* __restrict__ bias,
    float* __restrict__ Cf, bf16* __restrict__ Ch, bf16* __restrict__ Cl,
    int M, int N, int K,
    const int* __restrict__ seq, const float* __restrict__ embed)
{
    constexpr int BK = 32, STR = GSTR;
    extern __shared__ bf16 sm[];
    bf16* sA = sm;                       // [2 buf][2 hl][64*STR]
    bf16* sB = sm + 2 * 2 * 64 * STR;    // [2 buf][2 hl][128*STR]

    const int tid = threadIdx.x;
    const int lane = tid & 31;
    const int wid = tid >> 5;
    const int warpM = wid & 1, warpN = wid >> 1;
    const int rowBase = blockIdx.y * 64;
    const int colBase = blockIdx.x * 128;

    // A gather geometry (GATHER): thread owns (row = tid>>2, 8 cols)
    const float* arow = nullptr;
    const int agr = tid >> 2, agc = (tid & 3) * 8;
    if (GATHER) arow = embed + (long)seq[rowBase + agr] * K;

    float4 aN[2];
    auto loadAreg = [&](int s) {
        aN[0] = *(const float4*)(arow + s * BK + agc);
        aN[1] = *(const float4*)(arow + s * BK + agc + 4);
    };
    auto stsA = [&](int buf) {
        const float* af = (const float*)aN;
        unsigned ph[4], pl[4];
        #pragma unroll
        for (int i = 0; i < 4; i++) {
            bf16 h0, l0, h1, l1;
            split2(af[2 * i],     h0, l0);
            split2(af[2 * i + 1], h1, l1);
            __nv_bfloat162 H = __halves2bfloat162(h0, h1);
            __nv_bfloat162 L = __halves2bfloat162(l0, l1);
            ph[i] = *(unsigned*)&H;
            pl[i] = *(unsigned*)&L;
        }
        bf16* dH = sA + (buf * 2 + 0) * 64 * STR + agr * STR + agc;
        bf16* dL = sA + (buf * 2 + 1) * 64 * STR + agr * STR + agc;
        *(uint4*)dH = make_uint4(ph[0], ph[1], ph[2], ph[3]);
        *(uint4*)dL = make_uint4(pl[0], pl[1], pl[2], pl[3]);
    };

    auto issueA = [&](int buf, int s) {   // cp.async path (non-gather)
        const int k0 = s * BK;
        const int r = tid >> 2, c = (tid & 3) * 8;
        const long goff = (long)(rowBase + r) * K + k0 + c;
        cp16(sA + (buf * 2 + 0) * 64 * STR + r * STR + c, Agh + goff);
        cp16(sA + (buf * 2 + 1) * 64 * STR + r * STR + c, Agl + goff);
    };
    auto issueB = [&](int buf, int s) {
        const int k0 = s * BK;
        #pragma unroll
        for (int q = 0; q < 2; q++) {
            const int idx = tid + 256 * q;
            const int n = idx >> 2, c = (idx & 3) * 8;
            const long goff = (long)(colBase + n) * K + k0 + c;
            cp16(sB + (buf * 2 + 0) * 128 * STR + n * STR + c, Bgh + goff);
            cp16(sB + (buf * 2 + 1) * 128 * STR + n * STR + c, Bgl + goff);
        }
    };

    float d[2][4][4];
    #pragma unroll
    for (int mt = 0; mt < 2; mt++)
        #pragma unroll
        for (int nt = 0; nt < 4; nt++)
            #pragma unroll
            for (int e = 0; e < 4; e++) d[mt][nt][e] = 0.f;

    const int nst = K / BK;
    if (GATHER) {
        loadAreg(0);
        issueB(0, 0); CP_COMMIT();
        stsA(0);
        if (nst > 1) loadAreg(1);
    } else {
        issueA(0, 0); issueB(0, 0); CP_COMMIT();
    }

    const unsigned smemBase = (unsigned)__cvta_generic_to_shared(sm);
    const int lane8 = lane & 7, ls = lane >> 3;
    const int aRow = warpM * 32 + lane8 + ((ls & 1) << 3);
    const int aCol = (ls & 2) << 2;
    const int bRow = warpN * 32 + lane8 + ((ls & 2) << 2);
    const int bCol = (ls & 1) << 3;
    const unsigned sBbase = smemBase + 2u * (2 * 2 * 64 * STR);

    for (int s = 0; s < nst; s++) {
        const int buf = s & 1;
        if (s + 1 < nst) {
            if (GATHER) stsA(buf ^ 1);
            else        issueA(buf ^ 1, s + 1);
            issueB(buf ^ 1, s + 1);
            CP_COMMIT(); CP_WAIT(1);
        } else {
            CP_WAIT(0);
        }
        __syncthreads();
        if (GATHER && s + 2 < nst) loadAreg(s + 2);

        const unsigned aBuf = smemBase + 2u * (buf * 2 * 64 * STR);
        const unsigned bBuf = sBbase   + 2u * (buf * 2 * 128 * STR);

        #pragma unroll
        for (int h = 0; h < 2; h++) {
            const int hk = h * 16;
            unsigned ah[2][4], al[2][4], bh[2][4], bl[2][4];
            #pragma unroll
            for (int mt = 0; mt < 2; mt++) {
                const unsigned off = 2u * ((aRow + mt * 16) * STR + hk + aCol);
                ldsm4(ah[mt], aBuf + off);
                ldsm4(al[mt], aBuf + 2u * (64 * STR) + off);
            }
            #pragma unroll
            for (int p = 0; p < 2; p++) {
                const unsigned off = 2u * ((bRow + p * 16) * STR + hk + bCol);
                ldsm4(bh[p], bBuf + off);
                ldsm4(bl[p], bBuf + 2u * (128 * STR) + off);
            }
            #pragma unroll
            for (int mt = 0; mt < 2; mt++)
                #pragma unroll
                for (int nt = 0; nt < 4; nt++) {
                    const int p = nt >> 1, o = (nt & 1) * 2;
                    mma_bf16(d[mt][nt], ah[mt], &bh[p][o]);
                    mma_bf16(d[mt][nt], ah[mt], &bl[p][o]);
                    mma_bf16(d[mt][nt], al[mt], &bh[p][o]);
                }
        }
        __syncthreads();
    }

    const int lr = lane >> 2;
    const int lk = 2 * (lane & 3);
    #pragma unroll
    for (int mt = 0; mt < 2; mt++) {
        #pragma unroll
        for (int nt = 0; nt < 4; nt++) {
            const int cc = colBase + warpN * 32 + nt * 8 + lk;
            const float b0 = bias[cc], b1 = bias[cc + 1];
            #pragma unroll
            for (int half = 0; half < 2; half++) {
                const int r = rowBase + warpM * 32 + mt * 16 + lr + half * 8;
                float v0 = d[mt][nt][half * 2 + 0] + b0;
                float v1 = d[mt][nt][half * 2 + 1] + b1;
                if (MODE == 1) {
                    v0 = fmaxf(v0, 0.f); v1 = fmaxf(v1, 0.f);
                    bf16 h0, l0, h1, l1;
                    split2(v0, h0, l0); split2(v1, h1, l1);
                    const long off = (long)r * N + cc;
                    *(__nv_bfloat162*)(Ch + off) = __halves2bfloat162(h0, h1);
                    *(__nv_bfloat162*)(Cl + off) = __halves2bfloat162(l0, l1);
                } else {
                    const float* erow = embed + (long)seq[r] * Hd + cc;
                    v0 += erow[0]; v1 += erow[1];
                    *(float2*)(Cf + (long)r * N + cc) = make_float2(v0, v1);
                }
            }
        }
    }
}

// ---------------------------------------------------------------------------
// LN kernel (unchanged)
// ---------------------------------------------------------------------------
__global__ __launch_bounds__(256) void ln_kernel(
    const float* __restrict__ X, const float* __restrict__ gamma,
    const float* __restrict__ beta, float* __restrict__ He,
    bf16* __restrict__ Khg, bf16* __restrict__ Klg,
    float* __restrict__ invn)
{
    const int r = blockIdx.x * 8 + (threadIdx.x >> 5);
    const int lane = threadIdx.x & 31;
    const float* x = X + (long)r * Hd;

    float v[8], s = 0.f, sq = 0.f;
    #pragma unroll
    for (int e = 0; e < 8; e++) {
        v[e] = x[lane + 32 * e];
        s += v[e];
        sq += v[e] * v[e];
    }
    #pragma unroll
    for (int o = 16; o > 0; o >>= 1) {
        s  += __shfl_xor_sync(0xffffffff, s,  o);
        sq += __shfl_xor_sync(0xffffffff, sq, o);
    }
    const float mu  = s * (1.f / Hd);
    const float var = sq * (1.f / Hd) - mu * mu;
    const float rstd = rsqrtf(var + 1e-5f);

    float ns = 0.f;
    #pragma unroll
    for (int e = 0; e < 8; e++) {
        const int c = lane + 32 * e;
        const float o = (v[e] - mu) * rstd * gamma[c] + beta[c];
        bf16 h, l; split2(o, h, l);
        He[(long)r * Hd + c]  = o;
        Khg[(long)r * Hd + c] = h;
        Klg[(long)r * Hd + c] = l;
        ns += o * o;
    }
    #pragma unroll
    for (int o = 16; o > 0; o >>= 1) ns += __shfl_xor_sync(0xffffffff, ns, o);
    if (lane == 0) invn[r] = 1.f / fmaxf(sqrtf(ns), 1e-12f);
}

// ---------------------------------------------------------------------------
// Prep kernel (unchanged)
// ---------------------------------------------------------------------------
__global__ __launch_bounds__(256) void prep_kernel(
    const bf16* __restrict__ Khg, const bf16* __restrict__ Klg,
    const float* __restrict__ invn_g, float* __restrict__ Tout)
{
    extern __shared__ char shc[];
    bf16*  Kh = (bf16*)shc;
    bf16*  Kl = Kh + 64 * STRB;
    float* G  = (float*)(Kl + 64 * STRB);
    float* Ts = G  + 64 * 65;
    float* Us = Ts + 64 * 65;
    float* iv = Us + 32 * 33;

    const int bId = blockIdx.x >> 3;
    const int cId = blockIdx.x & 7;
    const int tid = threadIdx.x;
    const int w = tid >> 5, lane = tid & 31;

    #pragma unroll
    for (int q = 0; q < 8; q++) {
        const int idx = tid + 256 * q;
        const int j = idx >> 5, c8 = idx & 31;
        const int t = 510 - (64 * cId + j);
        bf16* dh = Kh + j * STRB + c8 * 8;
        bf16* dl = Kl + j * STRB + c8 * 8;
        if (t >= 0) {
            const long goff = ((long)(bId * Ld + t)) * Hd + c8 * 8;
            cp16(dh, Khg + goff);
            cp16(dl, Klg + goff);
        } else {
            *(float4*)dh = make_float4(0.f, 0.f, 0.f, 0.f);
            *(float4*)dl = make_float4(0.f, 0.f, 0.f, 0.f);
        }
    }
    CP_COMMIT();
    if (tid < 64) {
        const int t = 510 - (64 * cId + tid);
        iv[tid] = (t >= 0) ? invn_g[bId * Ld + t] : 0.f;
    }
    CP_WAIT(0);
    __syncthreads();

    {
        const int warpM = w & 3, warpN = w >> 2;
        const unsigned khB = (unsigned)__cvta_generic_to_shared(Kh);
        const unsigned klB = (unsigned)__cvta_generic_to_shared(Kl);
        const int lane8 = lane & 7, ls = lane >> 3;
        const int aRow = warpM * 16 + lane8 + ((ls & 1) << 3);
        const int aCol = (ls & 2) << 2;
        const int bRow = warpN * 32 + lane8 + ((ls & 2) << 2);
        const int bCol = (ls & 1) << 3;

        float d[4][4];
        #pragma unroll
        for (int nt = 0; nt < 4; nt++)
            #pragma unroll
            for (int e = 0; e < 4; e++) d[nt][e] = 0.f;

        #pragma unroll
        for (int s = 0; s < 16; s++) {
            const int hk = s * 16;
            unsigned ah[4], al[4], bh[2][4], bl[2][4];
            {
                const unsigned off = 2u * (aRow * STRB + hk + aCol);
                ldsm4(ah, khB + off);
                ldsm4(al, klB + off);
            }
            #pragma unroll
            for (int p = 0; p < 2; p++) {
                const unsigned off = 2u * ((bRow + p * 16) * STRB + hk + bCol);
                ldsm4(bh[p], khB + off);
                ldsm4(bl[p], klB + off);
            }
            #pragma unroll
            for (int nt = 0; nt < 4; nt++) {
                const int p = nt >> 1, o = (nt & 1) * 2;
                mma_bf16(d[nt], ah, &bh[p][o]);
                mma_bf16(d[nt], ah, &bl[p][o]);
                mma_bf16(d[nt], al, &bh[p][o]);
            }
        }

        const int lr = lane >> 2, lk = 2 * (lane & 3);
        #pragma unroll
        for (int nt = 0; nt < 4; nt++) {
            const int c = warpN * 32 + nt * 8 + lk;
            #pragma unroll
            for (int half = 0; half < 2; half++) {
                const int r = warpM * 16 + lr + half * 8;
                const float sc = CEMA * iv[r];
                G[r * 65 + c]     = sc * iv[c]     * d[nt][half * 2 + 0];
                G[r * 65 + c + 1] = sc * iv[c + 1] * d[nt][half * 2 + 1];
            }
        }
    }
    __syncthreads();

    if (w == 0) {
        const int c = lane;
        float x[32];
        #pragma unroll
        for (int j = 0; j < 32; j++) {
            float sum = (j == c) ? 1.f : 0.f;
            #pragma unroll
            for (int l = 0; l < 32; l++)
                if (l < j) sum -= G[j * 65 + l] * x[l];
            x[j] = sum;
        }
        #pragma unroll
        for (int j = 0; j < 32; j++) Ts[j * 65 + c] = x[j];
    } else if (w == 1) {
        const int c = lane;
        float x[32];
        #pragma unroll
        for (int j = 0; j < 32; j++) {
            float sum = (j == c) ? 1.f : 0.f;
            #pragma unroll
            for (int l = 0; l < 32; l++)
                if (l < j) sum -= G[(32 + j) * 65 + 32 + l] * x[l];
            x[j] = sum;
        }
        #pragma unroll
        for (int j = 0; j < 32; j++) Ts[(32 + j) * 65 + 32 + c] = x[j];
    } else {
        for (int e = tid - 64; e < 1024; e += 192) {
            if (e >= 0) Ts[(e >> 5) * 65 + 32 + (e & 31)] = 0.f;
        }
    }
    __syncthreads();

    #pragma unroll
    for (int q = 0; q < 4; q++) {
        const int e = tid + 256 * q;
        const int r = e >> 5, c = e & 31;
        float s = 0.f;
        #pragma unroll
        for (int l = 0; l < 32; l++)
            s += G[(32 + r) * 65 + l] * Ts[l * 65 + c];
        Us[r * 33 + c] = s;
    }
    __syncthreads();

    #pragma unroll
    for (int q = 0; q < 4; q++) {
        const int e = tid + 256 * q;
        const int r = e >> 5, c = e & 31;
        float s = 0.f;
        #pragma unroll
        for (int l = 0; l < 32; l++)
            s += Ts[(32 + r) * 65 + 32 + l] * Us[l * 33 + c];
        Ts[(32 + r) * 65 + c] = -s;
    }
    __syncthreads();

    float* Tg = Tout + ((long)(bId * NCH + cId) << 12);
    #pragma unroll
    for (int q = 0; q < 16; q++) {
        const int e = tid + 256 * q;
        Tg[e] = Ts[(e >> 6) * 65 + (e & 63)];
    }
}

// ---------------------------------------------------------------------------
// Chunked backward scan + fused rp, 512 threads (unchanged)
// ---------------------------------------------------------------------------
__global__ __launch_bounds__(512) void scan_kernel(
    const float* __restrict__ He, const float* __restrict__ invn,
    const float* __restrict__ Tin,
    const float* __restrict__ Wrp, const float* __restrict__ brp,
    float* __restrict__ mmout)
{
    extern __shared__ float sh[];
    float* Kb   = sh;
    float* Tb   = Kb + 2 * 64 * KSTR;
    float* ivb  = Tb + 2 * 64 * TSTR;
    float* vsm  = ivb + 128;
    float* bsm  = vsm + 256;
    float* csm  = bsm + 64;
    float* cnsm = csm + 64;
    float* par  = cnsm + 64;

    const int bId = blockIdx.x;
    const int tid = threadIdx.x;
    const float* Hb = He + (long)bId * Ld * Hd;
    const float* In = invn + bId * Ld;
    const float* Tc = Tin + ((long)bId * NCH << 12);

    auto issue = [&](int buf, int c) {
        float* K = Kb + buf * 64 * KSTR;
        #pragma unroll
        for (int q = 0; q < 8; q++) {
            const int idx = tid + 512 * q;
            const int j = idx >> 6, c4 = idx & 63;
            const int t = 510 - (64 * c + j);
            float* dst = K + j * KSTR + c4 * 4;
            if (t >= 0) cp16(dst, Hb + (long)t * Hd + c4 * 4);
            else        *(float4*)dst = make_float4(0.f, 0.f, 0.f, 0.f);
        }
        #pragma unroll
        for (int q = 0; q < 2; q++) {
            const int idx = tid + 512 * q;
            const int r = idx >> 4, c4 = idx & 15;
            cp16(Tb + buf * 64 * TSTR + r * TSTR + c4 * 4,
                 Tc + ((long)c << 12) + r * 64 + c4 * 4);
        }
        if (tid < 64) {
            const int t = 510 - (64 * c + tid);
            ivb[buf * 64 + tid] = (t >= 0) ? In[t] : 0.f;
        }
    };

    issue(0, 0);
    CP_COMMIT();
    if (tid < 256) vsm[tid] = Hb[511 * Hd + tid];
    float mi = 0.f;
    CP_WAIT(0);
    __syncthreads();

    const int jrow = tid >> 3, sub = tid & 7;
    const int eC = tid & 255, hC = tid >> 8;
    int buf = 0;
    #pragma unroll 1
    for (int c = 0; c < NCH; c++) {
        if (c + 1 < NCH) { issue(buf ^ 1, c + 1); CP_COMMIT(); }

        float* K  = Kb + buf * 64 * KSTR;
        float* T  = Tb + buf * 64 * TSTR;
        float* iv = ivb + buf * 64;

        {
            const float4* Kr4 = (const float4*)(K + jrow * KSTR);
            const float4* v4  = (const float4*)vsm;
            float p0 = 0.f, p1 = 0.f;
            #pragma unroll
            for (int i = 0; i < 8; i += 2) {
                float4 a0 = Kr4[sub + 8 * i],       b0 = v4[sub + 8 * i];
                float4 a1 = Kr4[sub + 8 * (i + 1)], b1 = v4[sub + 8 * (i + 1)];
                p0 += a0.x * b0.x + a0.y * b0.y + a0.z * b0.z + a0.w * b0.w;
                p1 += a1.x * b1.x + a1.y * b1.y + a1.z * b1.z + a1.w * b1.w;
            }
            float s = p0 + p1;
            s += __shfl_xor_sync(0xffffffff, s, 1);
            s += __shfl_xor_sync(0xffffffff, s, 2);
            s += __shfl_xor_sync(0xffffffff, s, 4);
            if (sub == 0) bsm[jrow] = s * iv[jrow];
        }
        __syncthreads();

        {
            const float* Tr = T + jrow * TSTR + sub * 8;
            const float* br = bsm + sub * 8;
            float t0 = 0.f, t1 = 0.f;
            #pragma unroll
            for (int q = 0; q < 8; q += 2) {
                t0 += Tr[q]     * br[q];
                t1 += Tr[q + 1] * br[q + 1];
            }
            float t = t0 + t1;
            t += __shfl_xor_sync(0xffffffff, t, 1);
            t += __shfl_xor_sync(0xffffffff, t, 2);
            t += __shfl_xor_sync(0xffffffff, t, 4);
            if (sub == 0) {
                const float cs = CEMA * t;
                csm[jrow]  = cs;
                cnsm[jrow] = cs * iv[jrow];
            }
        }
        __syncthreads();

        {
            const int j0 = hC * 32;
            float dm = 0.f, dv = 0.f;
            #pragma unroll
            for (int jq = 0; jq < 8; jq++) {
                const float4 cs4 = ((const float4*)csm)[hC * 8 + jq];
                const float4 cn4 = ((const float4*)cnsm)[hC * 8 + jq];
                const float k0 = K[(j0 + 4 * jq + 0) * KSTR + eC];
                const float k1 = K[(j0 + 4 * jq + 1) * KSTR + eC];
                const float k2 = K[(j0 + 4 * jq + 2) * KSTR + eC];
                const float k3 = K[(j0 + 4 * jq + 3) * KSTR + eC];
                dm += cs4.x * k0 + cs4.y * k1 + cs4.z * k2 + cs4.w * k3;
                dv += cn4.x * k0 + cn4.y * k1 + cn4.z * k2 + cn4.w * k3;
            }
            mi += dm;
            par[tid] = dv;
        }
        __syncthreads();
        if (tid < 256) vsm[tid] -= par[tid] + par[256 + tid];
        if (c + 1 < NCH) CP_WAIT(0);
        __syncthreads();
        buf ^= 1;
    }

    par[tid] = mi;
    __syncthreads();
    if (tid < 256) vsm[tid] = par[tid] + par[256 + tid];
    __syncthreads();

    {
        const int k0 = hC * 128;
        float acc = 0.f;
        #pragma unroll 8
        for (int k = 0; k < 128; k++)
            acc += vsm[k0 + k] * Wrp[(k0 + k) * Hd + eC];
        par[tid] = acc;
    }
    __syncthreads();
    if (tid < 256)
        mmout[bId * Hd + tid] = brp[tid] + par[tid] + par[256 + tid];
}

// ---------------------------------------------------------------------------
// out[8,32000] = mm @ Wout + bout (unchanged)
// ---------------------------------------------------------------------------
__global__ __launch_bounds__(128) void out_kernel(
    const float* __restrict__ mm, const float* __restrict__ Wout,
    const float* __restrict__ bout, float* __restrict__ out)
{
    __shared__ float ms[Bq][Hd];
    int tid = threadIdx.x;
    #pragma unroll
    for (int i = tid; i < Bq * Hd; i += 128) ms[i >> 8][i & 255] = mm[i];
    __syncthreads();

    int col = blockIdx.x * 128 + tid;
    float acc[Bq];
    float bo = bout[col];
    #pragma unroll
    for (int b = 0; b < Bq; b++) acc[b] = bo;

    #pragma unroll 4
    for (int k = 0; k < Hd; k++) {
        float w = Wout[(long)k * Vv + col];
        #pragma unroll
        for (int b = 0; b < Bq; b++) acc[b] += ms[b][k] * w;
    }
    #pragma unroll
    for (int b = 0; b < Bq; b++) out[(long)b * Vv + col] = acc[b];
}

// ---------------------------------------------------------------------------
extern "C" void kernel_launch(void* const* d_in, const int* in_sizes, int n_in,
                              void* d_out, int out_size)
{
    const int*   seq   = (const int*)  d_in[0];
    const float* embed = (const float*)d_in[1];
    const float* W1    = (const float*)d_in[2];
    const float* b1    = (const float*)d_in[3];
    const float* W2    = (const float*)d_in[4];
    const float* b2    = (const float*)d_in[5];
    const float* gamma = (const float*)d_in[6];
    const float* beta  = (const float*)d_in[7];
    const float* Wrp   = (const float*)d_in[8];
    const float* brp   = (const float*)d_in[9];
    const float* Wout  = (const float*)d_in[10];
    const float* bout  = (const float*)d_in[11];
    float* out = (float*)d_out;

    bf16 *W1h, *W1l, *W2h, *W2l, *t1h, *t1l, *Khg, *Klg;
    float *x, *he, *invn, *Tm, *mm;
    cudaGetSymbolAddress((void**)&W1h, g_W1h);
    cudaGetSymbolAddress((void**)&W1l, g_W1l);
    cudaGetSymbolAddress((void**)&W2h, g_W2h);
    cudaGetSymbolAddress((void**)&W2l, g_W2l);
    cudaGetSymbolAddress((void**)&t1h, g_t1h);
    cudaGetSymbolAddress((void**)&t1l, g_t1l);
    cudaGetSymbolAddress((void**)&Khg, g_Khg);
    cudaGetSymbolAddress((void**)&Klg, g_Klg);
    cudaGetSymbolAddress((void**)&x,    g_x);
    cudaGetSymbolAddress((void**)&he,   g_he);
    cudaGetSymbolAddress((void**)&invn, g_in);
    cudaGetSymbolAddress((void**)&Tm,   g_T);
    cudaGetSymbolAddress((void**)&mm,   g_mm);

    const int gemmSmem = (2 * 2 * 64 * GSTR + 2 * 2 * 128 * GSTR) * 2; // 61440
    const int prepSmem = 2 * 64 * STRB * 2
                       + (64 * 65 + 64 * 65 + 32 * 33 + 64) * 4;
    const int scanSmem = (2 * 64 * KSTR + 2 * 64 * TSTR + 128
                          + 256 + 64 * 3 + 512) * 4;
    cudaFuncSetAttribute((const void*)mma_gemm_kernel<1, true>,
        cudaFuncAttributeMaxDynamicSharedMemorySize, gemmSmem);
    cudaFuncSetAttribute((const void*)mma_gemm_kernel<2, false>,
        cudaFuncAttributeMaxDynamicSharedMemorySize, gemmSmem);
    cudaFuncSetAttribute(prep_kernel,
        cudaFuncAttributeMaxDynamicSharedMemorySize, prepSmem);
    cudaFuncSetAttribute(scan_kernel,
        cudaFuncAttributeMaxDynamicSharedMemorySize, scanSmem);

    // 0a) W1 transpose/split   0b) W2 transpose/split (separate: slot-4 = gemm2)
    convW_kernel<<<128, 256>>>(W1, W1h, W1l, Hd, 512, 16);
    convW_kernel<<<128, 256>>>(W2, W2h, W2l, 512, Hd, 8);

    // 1) t1 = relu(embed[seq] @ W1 + b1) -> bf16 hi/lo (fused gather)
    mma_gemm_kernel<1, true><<<dim3(512 / 128, NTOK / 64), 256, gemmSmem>>>(
        nullptr, nullptr, W1h, W1l, b1, nullptr, t1h, t1l,
        NTOK, 512, Hd, seq, embed);

    // 2) x = t1 @ W2 + b2 + embed[seq]   (profiled slot)
    mma_gemm_kernel<2, false><<<dim3(Hd / 128, NTOK / 64), 256, gemmSmem>>>(
        t1h, t1l, W2h, W2l, b2, x, nullptr, nullptr,
        NTOK, Hd, 512, seq, embed);

    // 3) LN all rows: He, bf16 keys, invn
    ln_kernel<<<NTOK / 8, 256>>>(x, gamma, beta, he, Khg, Klg, invn);

    // 4) tensor-core Gram + chunk inverse T
    prep_kernel<<<Bq * NCH, 256, prepSmem>>>(Khg, Klg, invn, Tm);

    // 5) chunked backward scan -> mm (rp fused), 512 threads
    scan_kernel<<<Bq, 512, scanSmem>>>(he, invn, Tm, Wrp, brp, mm);

    // 6) out = mm @ Wout + bout
    out_kernel<<<Vv / 128, 128>>>(mm, Wout, bout, out);
}

// round 17
// speedup vs baseline: 1.0507x; 1.0507x over previous
#include <cuda_runtime.h>
#include <cuda_bf16.h>

// Problem constants
#define Hd   256
#define Ld   512
#define Bq   8
#define NTOK 4096            // B*L
#define Vv   32000
#define CEMA 0.05f           // 1 - alpha
#define CSZ  64              // chunk size
#define NCH  8               // chunks per batch
#define KSTR 260             // K-tile smem row stride (scan, fp32 words)
#define TSTR 68              // T smem row stride
#define STRB 264             // prep bf16 key row stride
#define GSTR 40              // gemm bf16 smem row stride (BK=32 + pad)

typedef __nv_bfloat16 bf16;

// Scratch (device globals)
__device__ bf16  g_W1h[512 * Hd],   g_W1l[512 * Hd];
__device__ bf16  g_W2h[Hd * 512],   g_W2l[Hd * 512];
__device__ bf16  g_t1h[NTOK * 512], g_t1l[NTOK * 512];
__device__ bf16  g_Khg[NTOK * Hd],  g_Klg[NTOK * Hd];   // LN'd keys, bf16 hi/lo
__device__ float g_x [NTOK * Hd];
__device__ float g_he[NTOK * Hd];
__device__ float g_in[NTOK];
__device__ float g_T [Bq * NCH * CSZ * CSZ];
__device__ float g_mm[Bq * Hd];

// cp.async helpers
__device__ __forceinline__ void cp16(void* dst, const void* src) {
    unsigned d = (unsigned)__cvta_generic_to_shared(dst);
    asm volatile("cp.async.ca.shared.global [%0], [%1], 16;\n" :: "r"(d), "l"(src));
}
#define CP_COMMIT() asm volatile("cp.async.commit_group;\n" ::: "memory")
#define CP_WAIT(n)  asm volatile("cp.async.wait_group %0;\n" :: "n"(n) : "memory")

__device__ __forceinline__ void mma_bf16(float* d, const unsigned* a, const unsigned* b) {
    asm volatile(
        "mma.sync.aligned.m16n8k16.row.col.f32.bf16.bf16.f32 "
        "{%0,%1,%2,%3}, {%4,%5,%6,%7}, {%8,%9}, {%0,%1,%2,%3};"
        : "+f"(d[0]), "+f"(d[1]), "+f"(d[2]), "+f"(d[3])
        : "r"(a[0]), "r"(a[1]), "r"(a[2]), "r"(a[3]), "r"(b[0]), "r"(b[1]));
}

__device__ __forceinline__ void ldsm4(unsigned* r, unsigned addr) {
    asm volatile("ldmatrix.sync.aligned.m8n8.x4.shared.b16 {%0,%1,%2,%3}, [%4];"
        : "=r"(r[0]), "=r"(r[1]), "=r"(r[2]), "=r"(r[3]) : "r"(addr));
}

__device__ __forceinline__ void split2(float v, bf16& h, bf16& l) {
    h = __float2bfloat16_rn(v);
    l = __float2bfloat16_rn(v - __bfloat162float(h));
}

// ---------------------------------------------------------------------------
// W transpose/split kernels
// ---------------------------------------------------------------------------
__global__ __launch_bounds__(256) void convW_kernel(
    const float* __restrict__ W, bf16* __restrict__ Wh, bf16* __restrict__ Wl,
    int K, int N, int nBlkX)
{
    __shared__ float tile[32][33];
    const int p = blockIdx.x;
    const int n0 = (p % nBlkX) * 32, k0 = (p / nBlkX) * 32;
    const int tx = threadIdx.x & 31, ty = threadIdx.x >> 5;
    #pragma unroll
    for (int i = 0; i < 4; i++)
        tile[ty + 8 * i][tx] = W[(long)(k0 + ty + 8 * i) * N + n0 + tx];
    __syncthreads();
    #pragma unroll
    for (int i = 0; i < 4; i++) {
        const int row = ty + 8 * i;
        const float v = tile[tx][row];
        bf16 h, l; split2(v, h, l);
        Wh[(long)(n0 + row) * K + k0 + tx] = h;
        Wl[(long)(n0 + row) * K + k0 + tx] = l;
    }
}

// ---------------------------------------------------------------------------
// GEMM1: 64x128 tile, 256 threads, 8 warps, fused fp32 gather of A.
// t1 = relu(embed[seq] @ W1 + b1) -> bf16 hi/lo
// ---------------------------------------------------------------------------
__global__ __launch_bounds__(256, 2) void gemm1_kernel(
    const bf16* __restrict__ Bgh, const bf16* __restrict__ Bgl,
    const float* __restrict__ bias,
    bf16* __restrict__ Ch, bf16* __restrict__ Cl,
    int M, int N, int K,
    const int* __restrict__ seq, const float* __restrict__ embed)
{
    constexpr int BK = 32, STR = GSTR;
    extern __shared__ bf16 sm[];
    bf16* sA = sm;                       // [2 buf][2 hl][64*STR]
    bf16* sB = sm + 2 * 2 * 64 * STR;    // [2 buf][2 hl][128*STR]

    const int tid = threadIdx.x;
    const int lane = tid & 31;
    const int wid = tid >> 5;
    const int warpM = wid & 1, warpN = wid >> 1;
    const int rowBase = blockIdx.y * 64;
    const int colBase = blockIdx.x * 128;

    const float* arow = embed + (long)seq[rowBase + (tid >> 2)] * K;
    const int agr = tid >> 2, agc = (tid & 3) * 8;

    float4 aN[2];
    auto loadAreg = [&](int s) {
        aN[0] = *(const float4*)(arow + s * BK + agc);
        aN[1] = *(const float4*)(arow + s * BK + agc + 4);
    };
    auto stsA = [&](int buf) {
        const float* af = (const float*)aN;
        unsigned ph[4], pl[4];
        #pragma unroll
        for (int i = 0; i < 4; i++) {
            bf16 h0, l0, h1, l1;
            split2(af[2 * i],     h0, l0);
            split2(af[2 * i + 1], h1, l1);
            __nv_bfloat162 H = __halves2bfloat162(h0, h1);
            __nv_bfloat162 L = __halves2bfloat162(l0, l1);
            ph[i] = *(unsigned*)&H;
            pl[i] = *(unsigned*)&L;
        }
        bf16* dH = sA + (buf * 2 + 0) * 64 * STR + agr * STR + agc;
        bf16* dL = sA + (buf * 2 + 1) * 64 * STR + agr * STR + agc;
        *(uint4*)dH = make_uint4(ph[0], ph[1], ph[2], ph[3]);
        *(uint4*)dL = make_uint4(pl[0], pl[1], pl[2], pl[3]);
    };
    auto issueB = [&](int buf, int s) {
        const int k0 = s * BK;
        #pragma unroll
        for (int q = 0; q < 2; q++) {
            const int idx = tid + 256 * q;
            const int n = idx >> 2, c = (idx & 3) * 8;
            const long goff = (long)(colBase + n) * K + k0 + c;
            cp16(sB + (buf * 2 + 0) * 128 * STR + n * STR + c, Bgh + goff);
            cp16(sB + (buf * 2 + 1) * 128 * STR + n * STR + c, Bgl + goff);
        }
    };

    float d[2][4][4];
    #pragma unroll
    for (int mt = 0; mt < 2; mt++)
        #pragma unroll
        for (int nt = 0; nt < 4; nt++)
            #pragma unroll
            for (int e = 0; e < 4; e++) d[mt][nt][e] = 0.f;

    const int nst = K / BK;
    loadAreg(0);
    issueB(0, 0); CP_COMMIT();
    stsA(0);
    if (nst > 1) loadAreg(1);

    const unsigned smemBase = (unsigned)__cvta_generic_to_shared(sm);
    const int lane8 = lane & 7, ls = lane >> 3;
    const int aRow = warpM * 32 + lane8 + ((ls & 1) << 3);
    const int aCol = (ls & 2) << 2;
    const int bRow = warpN * 32 + lane8 + ((ls & 2) << 2);
    const int bCol = (ls & 1) << 3;
    const unsigned sBbase = smemBase + 2u * (2 * 2 * 64 * STR);

    for (int s = 0; s < nst; s++) {
        const int buf = s & 1;
        if (s + 1 < nst) {
            stsA(buf ^ 1);
            issueB(buf ^ 1, s + 1);
            CP_COMMIT(); CP_WAIT(1);
        } else {
            CP_WAIT(0);
        }
        __syncthreads();
        if (s + 2 < nst) loadAreg(s + 2);

        const unsigned aBuf = smemBase + 2u * (buf * 2 * 64 * STR);
        const unsigned bBuf = sBbase   + 2u * (buf * 2 * 128 * STR);

        #pragma unroll
        for (int h = 0; h < 2; h++) {
            const int hk = h * 16;
            unsigned ah[2][4], al[2][4], bh[2][4], bl[2][4];
            #pragma unroll
            for (int mt = 0; mt < 2; mt++) {
                const unsigned off = 2u * ((aRow + mt * 16) * STR + hk + aCol);
                ldsm4(ah[mt], aBuf + off);
                ldsm4(al[mt], aBuf + 2u * (64 * STR) + off);
            }
            #pragma unroll
            for (int p = 0; p < 2; p++) {
                const unsigned off = 2u * ((bRow + p * 16) * STR + hk + bCol);
                ldsm4(bh[p], bBuf + off);
                ldsm4(bl[p], bBuf + 2u * (128 * STR) + off);
            }
            #pragma unroll
            for (int mt = 0; mt < 2; mt++)
                #pragma unroll
                for (int nt = 0; nt < 4; nt++) {
                    const int p = nt >> 1, o = (nt & 1) * 2;
                    mma_bf16(d[mt][nt], ah[mt], &bh[p][o]);
                    mma_bf16(d[mt][nt], ah[mt], &bl[p][o]);
                    mma_bf16(d[mt][nt], al[mt], &bh[p][o]);
                }
        }
        __syncthreads();
    }

    const int lr = lane >> 2;
    const int lk = 2 * (lane & 3);
    #pragma unroll
    for (int mt = 0; mt < 2; mt++) {
        #pragma unroll
        for (int nt = 0; nt < 4; nt++) {
            const int cc = colBase + warpN * 32 + nt * 8 + lk;
            const float b0 = bias[cc], b1 = bias[cc + 1];
            #pragma unroll
            for (int half = 0; half < 2; half++) {
                const int r = rowBase + warpM * 32 + mt * 16 + lr + half * 8;
                float v0 = fmaxf(d[mt][nt][half * 2 + 0] + b0, 0.f);
                float v1 = fmaxf(d[mt][nt][half * 2 + 1] + b1, 0.f);
                bf16 h0, l0, h1, l1;
                split2(v0, h0, l0); split2(v1, h1, l1);
                const long off = (long)r * N + cc;
                *(__nv_bfloat162*)(Ch + off) = __halves2bfloat162(h0, h1);
                *(__nv_bfloat162*)(Cl + off) = __halves2bfloat162(l0, l1);
            }
        }
    }
}

// ---------------------------------------------------------------------------
// GEMM2: 64x64 tile, 128 threads (4 warps, 2x2), warp tile 32x32, BK=32.
// Grid 256 blocks -> fills the chip. x = t1 @ W2 + b2 + embed[seq], fp32.
// ---------------------------------------------------------------------------
__global__ __launch_bounds__(128, 4) void gemm2_kernel(
    const bf16* __restrict__ Agh, const bf16* __restrict__ Agl,
    const bf16* __restrict__ Bgh, const bf16* __restrict__ Bgl,
    const float* __restrict__ bias, float* __restrict__ Cf,
    int M, int N, int K,
    const int* __restrict__ seq, const float* __restrict__ embed)
{
    constexpr int BK = 32, STR = GSTR;
    extern __shared__ bf16 sm[];
    bf16* sA = sm;                       // [2 buf][2 hl][64*STR]
    bf16* sB = sm + 2 * 2 * 64 * STR;    // [2 buf][2 hl][64*STR]

    const int tid = threadIdx.x;
    const int lane = tid & 31;
    const int wid = tid >> 5;
    const int warpM = wid & 1, warpN = wid >> 1;   // 2x2 warps
    const int rowBase = blockIdx.y * 64;
    const int colBase = blockIdx.x * 64;

    auto issue = [&](int buf, int s) {
        const int k0 = s * BK;
        // A: 64 rows x 4 chunks = 256 per hl; 2 per thread per hl
        #pragma unroll
        for (int q = 0; q < 2; q++) {
            const int idx = tid + 128 * q;
            const int r = idx >> 2, c = (idx & 3) * 8;
            const long ga = (long)(rowBase + r) * K + k0 + c;
            const long gb = (long)(colBase + r) * K + k0 + c;
            cp16(sA + (buf * 2 + 0) * 64 * STR + r * STR + c, Agh + ga);
            cp16(sA + (buf * 2 + 1) * 64 * STR + r * STR + c, Agl + ga);
            cp16(sB + (buf * 2 + 0) * 64 * STR + r * STR + c, Bgh + gb);
            cp16(sB + (buf * 2 + 1) * 64 * STR + r * STR + c, Bgl + gb);
        }
    };

    float d[2][4][4];
    #pragma unroll
    for (int mt = 0; mt < 2; mt++)
        #pragma unroll
        for (int nt = 0; nt < 4; nt++)
            #pragma unroll
            for (int e = 0; e < 4; e++) d[mt][nt][e] = 0.f;

    const int nst = K / BK;
    issue(0, 0);
    CP_COMMIT();

    const unsigned smemBase = (unsigned)__cvta_generic_to_shared(sm);
    const int lane8 = lane & 7, ls = lane >> 3;
    const int aRow = warpM * 32 + lane8 + ((ls & 1) << 3);
    const int aCol = (ls & 2) << 2;
    const int bRow = warpN * 32 + lane8 + ((ls & 2) << 2);
    const int bCol = (ls & 1) << 3;
    const unsigned sBbase = smemBase + 2u * (2 * 2 * 64 * STR);

    for (int s = 0; s < nst; s++) {
        const int buf = s & 1;
        if (s + 1 < nst) { issue(buf ^ 1, s + 1); CP_COMMIT(); CP_WAIT(1); }
        else             { CP_WAIT(0); }
        __syncthreads();

        const unsigned aBuf = smemBase + 2u * (buf * 2 * 64 * STR);
        const unsigned bBuf = sBbase   + 2u * (buf * 2 * 64 * STR);

        #pragma unroll
        for (int h = 0; h < 2; h++) {
            const int hk = h * 16;
            unsigned ah[2][4], al[2][4], bh[2][4], bl[2][4];
            #pragma unroll
            for (int mt = 0; mt < 2; mt++) {
                const unsigned off = 2u * ((aRow + mt * 16) * STR + hk + aCol);
                ldsm4(ah[mt], aBuf + off);
                ldsm4(al[mt], aBuf + 2u * (64 * STR) + off);
            }
            #pragma unroll
            for (int p = 0; p < 2; p++) {
                const unsigned off = 2u * ((bRow + p * 16) * STR + hk + bCol);
                ldsm4(bh[p], bBuf + off);
                ldsm4(bl[p], bBuf + 2u * (64 * STR) + off);
            }
            #pragma unroll
            for (int mt = 0; mt < 2; mt++)
                #pragma unroll
                for (int nt = 0; nt < 4; nt++) {
                    const int p = nt >> 1, o = (nt & 1) * 2;
                    mma_bf16(d[mt][nt], ah[mt], &bh[p][o]);
                    mma_bf16(d[mt][nt], ah[mt], &bl[p][o]);
                    mma_bf16(d[mt][nt], al[mt], &bh[p][o]);
                }
        }
        __syncthreads();
    }

    const int lr = lane >> 2;
    const int lk = 2 * (lane & 3);
    #pragma unroll
    for (int mt = 0; mt < 2; mt++) {
        #pragma unroll
        for (int nt = 0; nt < 4; nt++) {
            const int cc = colBase + warpN * 32 + nt * 8 + lk;
            const float b0 = bias[cc], b1 = bias[cc + 1];
            #pragma unroll
            for (int half = 0; half < 2; half++) {
                const int r = rowBase + warpM * 32 + mt * 16 + lr + half * 8;
                const float* erow = embed + (long)seq[r] * Hd + cc;
                float v0 = d[mt][nt][half * 2 + 0] + b0 + erow[0];
                float v1 = d[mt][nt][half * 2 + 1] + b1 + erow[1];
                *(float2*)(Cf + (long)r * N + cc) = make_float2(v0, v1);
            }
        }
    }
}

// ---------------------------------------------------------------------------
// LN kernel (unchanged)
// ---------------------------------------------------------------------------
__global__ __launch_bounds__(256) void ln_kernel(
    const float* __restrict__ X, const float* __restrict__ gamma,
    const float* __restrict__ beta, float* __restrict__ He,
    bf16* __restrict__ Khg, bf16* __restrict__ Klg,
    float* __restrict__ invn)
{
    const int r = blockIdx.x * 8 + (threadIdx.x >> 5);
    const int lane = threadIdx.x & 31;
    const float* x = X + (long)r * Hd;

    float v[8], s = 0.f, sq = 0.f;
    #pragma unroll
    for (int e = 0; e < 8; e++) {
        v[e] = x[lane + 32 * e];
        s += v[e];
        sq += v[e] * v[e];
    }
    #pragma unroll
    for (int o = 16; o > 0; o >>= 1) {
        s  += __shfl_xor_sync(0xffffffff, s,  o);
        sq += __shfl_xor_sync(0xffffffff, sq, o);
    }
    const float mu  = s * (1.f / Hd);
    const float var = sq * (1.f / Hd) - mu * mu;
    const float rstd = rsqrtf(var + 1e-5f);

    float ns = 0.f;
    #pragma unroll
    for (int e = 0; e < 8; e++) {
        const int c = lane + 32 * e;
        const float o = (v[e] - mu) * rstd * gamma[c] + beta[c];
        bf16 h, l; split2(o, h, l);
        He[(long)r * Hd + c]  = o;
        Khg[(long)r * Hd + c] = h;
        Klg[(long)r * Hd + c] = l;
        ns += o * o;
    }
    #pragma unroll
    for (int o = 16; o > 0; o >>= 1) ns += __shfl_xor_sync(0xffffffff, ns, o);
    if (lane == 0) invn[r] = 1.f / fmaxf(sqrtf(ns), 1e-12f);
}

// ---------------------------------------------------------------------------
// Prep kernel (unchanged)
// ---------------------------------------------------------------------------
__global__ __launch_bounds__(256) void prep_kernel(
    const bf16* __restrict__ Khg, const bf16* __restrict__ Klg,
    const float* __restrict__ invn_g, float* __restrict__ Tout)
{
    extern __shared__ char shc[];
    bf16*  Kh = (bf16*)shc;
    bf16*  Kl = Kh + 64 * STRB;
    float* G  = (float*)(Kl + 64 * STRB);
    float* Ts = G  + 64 * 65;
    float* Us = Ts + 64 * 65;
    float* iv = Us + 32 * 33;

    const int bId = blockIdx.x >> 3;
    const int cId = blockIdx.x & 7;
    const int tid = threadIdx.x;
    const int w = tid >> 5, lane = tid & 31;

    #pragma unroll
    for (int q = 0; q < 8; q++) {
        const int idx = tid + 256 * q;
        const int j = idx >> 5, c8 = idx & 31;
        const int t = 510 - (64 * cId + j);
        bf16* dh = Kh + j * STRB + c8 * 8;
        bf16* dl = Kl + j * STRB + c8 * 8;
        if (t >= 0) {
            const long goff = ((long)(bId * Ld + t)) * Hd + c8 * 8;
            cp16(dh, Khg + goff);
            cp16(dl, Klg + goff);
        } else {
            *(float4*)dh = make_float4(0.f, 0.f, 0.f, 0.f);
            *(float4*)dl = make_float4(0.f, 0.f, 0.f, 0.f);
        }
    }
    CP_COMMIT();
    if (tid < 64) {
        const int t = 510 - (64 * cId + tid);
        iv[tid] = (t >= 0) ? invn_g[bId * Ld + t] : 0.f;
    }
    CP_WAIT(0);
    __syncthreads();

    {
        const int warpM = w & 3, warpN = w >> 2;
        const unsigned khB = (unsigned)__cvta_generic_to_shared(Kh);
        const unsigned klB = (unsigned)__cvta_generic_to_shared(Kl);
        const int lane8 = lane & 7, ls = lane >> 3;
        const int aRow = warpM * 16 + lane8 + ((ls & 1) << 3);
        const int aCol = (ls & 2) << 2;
        const int bRow = warpN * 32 + lane8 + ((ls & 2) << 2);
        const int bCol = (ls & 1) << 3;

        float d[4][4];
        #pragma unroll
        for (int nt = 0; nt < 4; nt++)
            #pragma unroll
            for (int e = 0; e < 4; e++) d[nt][e] = 0.f;

        #pragma unroll
        for (int s = 0; s < 16; s++) {
            const int hk = s * 16;
            unsigned ah[4], al[4], bh[2][4], bl[2][4];
            {
                const unsigned off = 2u * (aRow * STRB + hk + aCol);
                ldsm4(ah, khB + off);
                ldsm4(al, klB + off);
            }
            #pragma unroll
            for (int p = 0; p < 2; p++) {
                const unsigned off = 2u * ((bRow + p * 16) * STRB + hk + bCol);
                ldsm4(bh[p], khB + off);
                ldsm4(bl[p], klB + off);
            }
            #pragma unroll
            for (int nt = 0; nt < 4; nt++) {
                const int p = nt >> 1, o = (nt & 1) * 2;
                mma_bf16(d[nt], ah, &bh[p][o]);
                mma_bf16(d[nt], ah, &bl[p][o]);
                mma_bf16(d[nt], al, &bh[p][o]);
            }
        }

        const int lr = lane >> 2, lk = 2 * (lane & 3);
        #pragma unroll
        for (int nt = 0; nt < 4; nt++) {
            const int c = warpN * 32 + nt * 8 + lk;
            #pragma unroll
            for (int half = 0; half < 2; half++) {
                const int r = warpM * 16 + lr + half * 8;
                const float sc = CEMA * iv[r];
                G[r * 65 + c]     = sc * iv[c]     * d[nt][half * 2 + 0];
                G[r * 65 + c + 1] = sc * iv[c + 1] * d[nt][half * 2 + 1];
            }
        }
    }
    __syncthreads();

    if (w == 0) {
        const int c = lane;
        float x[32];
        #pragma unroll
        for (int j = 0; j < 32; j++) {
            float sum = (j == c) ? 1.f : 0.f;
            #pragma unroll
            for (int l = 0; l < 32; l++)
                if (l < j) sum -= G[j * 65 + l] * x[l];
            x[j] = sum;
        }
        #pragma unroll
        for (int j = 0; j < 32; j++) Ts[j * 65 + c] = x[j];
    } else if (w == 1) {
        const int c = lane;
        float x[32];
        #pragma unroll
        for (int j = 0; j < 32; j++) {
            float sum = (j == c) ? 1.f : 0.f;
            #pragma unroll
            for (int l = 0; l < 32; l++)
                if (l < j) sum -= G[(32 + j) * 65 + 32 + l] * x[l];
            x[j] = sum;
        }
        #pragma unroll
        for (int j = 0; j < 32; j++) Ts[(32 + j) * 65 + 32 + c] = x[j];
    } else {
        for (int e = tid - 64; e < 1024; e += 192) {
            if (e >= 0) Ts[(e >> 5) * 65 + 32 + (e & 31)] = 0.f;
        }
    }
    __syncthreads();

    #pragma unroll
    for (int q = 0; q < 4; q++) {
        const int e = tid + 256 * q;
        const int r = e >> 5, c = e & 31;
        float s = 0.f;
        #pragma unroll
        for (int l = 0; l < 32; l++)
            s += G[(32 + r) * 65 + l] * Ts[l * 65 + c];
        Us[r * 33 + c] = s;
    }
    __syncthreads();

    #pragma unroll
    for (int q = 0; q < 4; q++) {
        const int e = tid + 256 * q;
        const int r = e >> 5, c = e & 31;
        float s = 0.f;
        #pragma unroll
        for (int l = 0; l < 32; l++)
            s += Ts[(32 + r) * 65 + 32 + l] * Us[l * 33 + c];
        Ts[(32 + r) * 65 + c] = -s;
    }
    __syncthreads();

    float* Tg = Tout + ((long)(bId * NCH + cId) << 12);
    #pragma unroll
    for (int q = 0; q < 16; q++) {
        const int e = tid + 256 * q;
        Tg[e] = Ts[(e >> 6) * 65 + (e & 63)];
    }
}

// ---------------------------------------------------------------------------
// Chunked backward scan + fused rp, 512 threads (unchanged)
// ---------------------------------------------------------------------------
__global__ __launch_bounds__(512) void scan_kernel(
    const float* __restrict__ He, const float* __restrict__ invn,
    const float* __restrict__ Tin,
    const float* __restrict__ Wrp, const float* __restrict__ brp,
    float* __restrict__ mmout)
{
    extern __shared__ float sh[];
    float* Kb   = sh;
    float* Tb   = Kb + 2 * 64 * KSTR;
    float* ivb  = Tb + 2 * 64 * TSTR;
    float* vsm  = ivb + 128;
    float* bsm  = vsm + 256;
    float* csm  = bsm + 64;
    float* cnsm = csm + 64;
    float* par  = cnsm + 64;

    const int bId = blockIdx.x;
    const int tid = threadIdx.x;
    const float* Hb = He + (long)bId * Ld * Hd;
    const float* In = invn + bId * Ld;
    const float* Tc = Tin + ((long)bId * NCH << 12);

    auto issue = [&](int buf, int c) {
        float* K = Kb + buf * 64 * KSTR;
        #pragma unroll
        for (int q = 0; q < 8; q++) {
            const int idx = tid + 512 * q;
            const int j = idx >> 6, c4 = idx & 63;
            const int t = 510 - (64 * c + j);
            float* dst = K + j * KSTR + c4 * 4;
            if (t >= 0) cp16(dst, Hb + (long)t * Hd + c4 * 4);
            else        *(float4*)dst = make_float4(0.f, 0.f, 0.f, 0.f);
        }
        #pragma unroll
        for (int q = 0; q < 2; q++) {
            const int idx = tid + 512 * q;
            const int r = idx >> 4, c4 = idx & 15;
            cp16(Tb + buf * 64 * TSTR + r * TSTR + c4 * 4,
                 Tc + ((long)c << 12) + r * 64 + c4 * 4);
        }
        if (tid < 64) {
            const int t = 510 - (64 * c + tid);
            ivb[buf * 64 + tid] = (t >= 0) ? In[t] : 0.f;
        }
    };

    issue(0, 0);
    CP_COMMIT();
    if (tid < 256) vsm[tid] = Hb[511 * Hd + tid];
    float mi = 0.f;
    CP_WAIT(0);
    __syncthreads();

    const int jrow = tid >> 3, sub = tid & 7;
    const int eC = tid & 255, hC = tid >> 8;
    int buf = 0;
    #pragma unroll 1
    for (int c = 0; c < NCH; c++) {
        if (c + 1 < NCH) { issue(buf ^ 1, c + 1); CP_COMMIT(); }

        float* K  = Kb + buf * 64 * KSTR;
        float* T  = Tb + buf * 64 * TSTR;
        float* iv = ivb + buf * 64;

        {
            const float4* Kr4 = (const float4*)(K + jrow * KSTR);
            const float4* v4  = (const float4*)vsm;
            float p0 = 0.f, p1 = 0.f;
            #pragma unroll
            for (int i = 0; i < 8; i += 2) {
                float4 a0 = Kr4[sub + 8 * i],       b0 = v4[sub + 8 * i];
                float4 a1 = Kr4[sub + 8 * (i + 1)], b1 = v4[sub + 8 * (i + 1)];
                p0 += a0.x * b0.x + a0.y * b0.y + a0.z * b0.z + a0.w * b0.w;
                p1 += a1.x * b1.x + a1.y * b1.y + a1.z * b1.z + a1.w * b1.w;
            }
            float s = p0 + p1;
            s += __shfl_xor_sync(0xffffffff, s, 1);
            s += __shfl_xor_sync(0xffffffff, s, 2);
            s += __shfl_xor_sync(0xffffffff, s, 4);
            if (sub == 0) bsm[jrow] = s * iv[jrow];
        }
        __syncthreads();

        {
            const float* Tr = T + jrow * TSTR + sub * 8;
            const float* br = bsm + sub * 8;
            float t0 = 0.f, t1 = 0.f;
            #pragma unroll
            for (int q = 0; q < 8; q += 2) {
                t0 += Tr[q]     * br[q];
                t1 += Tr[q + 1] * br[q + 1];
            }
            float t = t0 + t1;
            t += __shfl_xor_sync(0xffffffff, t, 1);
            t += __shfl_xor_sync(0xffffffff, t, 2);
            t += __shfl_xor_sync(0xffffffff, t, 4);
            if (sub == 0) {
                const float cs = CEMA * t;
                csm[jrow]  = cs;
                cnsm[jrow] = cs * iv[jrow];
            }
        }
        __syncthreads();

        {
            const int j0 = hC * 32;
            float dm = 0.f, dv = 0.f;
            #pragma unroll
            for (int jq = 0; jq < 8; jq++) {
                const float4 cs4 = ((const float4*)csm)[hC * 8 + jq];
                const float4 cn4 = ((const float4*)cnsm)[hC * 8 + jq];
                const float k0 = K[(j0 + 4 * jq + 0) * KSTR + eC];
                const float k1 = K[(j0 + 4 * jq + 1) * KSTR + eC];
                const float k2 = K[(j0 + 4 * jq + 2) * KSTR + eC];
                const float k3 = K[(j0 + 4 * jq + 3) * KSTR + eC];
                dm += cs4.x * k0 + cs4.y * k1 + cs4.z * k2 + cs4.w * k3;
                dv += cn4.x * k0 + cn4.y * k1 + cn4.z * k2 + cn4.w * k3;
            }
            mi += dm;
            par[tid] = dv;
        }
        __syncthreads();
        if (tid < 256) vsm[tid] -= par[tid] + par[256 + tid];
        if (c + 1 < NCH) CP_WAIT(0);
        __syncthreads();
        buf ^= 1;
    }

    par[tid] = mi;
    __syncthreads();
    if (tid < 256) vsm[tid] = par[tid] + par[256 + tid];
    __syncthreads();

    {
        const int k0 = hC * 128;
        float acc = 0.f;
        #pragma unroll 8
        for (int k = 0; k < 128; k++)
            acc += vsm[k0 + k] * Wrp[(k0 + k) * Hd + eC];
        par[tid] = acc;
    }
    __syncthreads();
    if (tid < 256)
        mmout[bId * Hd + tid] = brp[tid] + par[tid] + par[256 + tid];
}

// ---------------------------------------------------------------------------
// out[8,32000] = mm @ Wout + bout (unchanged)
// ---------------------------------------------------------------------------
__global__ __launch_bounds__(128) void out_kernel(
    const float* __restrict__ mm, const float* __restrict__ Wout,
    const float* __restrict__ bout, float* __restrict__ out)
{
    __shared__ float ms[Bq][Hd];
    int tid = threadIdx.x;
    #pragma unroll
    for (int i = tid; i < Bq * Hd; i += 128) ms[i >> 8][i & 255] = mm[i];
    __syncthreads();

    int col = blockIdx.x * 128 + tid;
    float acc[Bq];
    float bo = bout[col];
    #pragma unroll
    for (int b = 0; b < Bq; b++) acc[b] = bo;

    #pragma unroll 4
    for (int k = 0; k < Hd; k++) {
        float w = Wout[(long)k * Vv + col];
        #pragma unroll
        for (int b = 0; b < Bq; b++) acc[b] += ms[b][k] * w;
    }
    #pragma unroll
    for (int b = 0; b < Bq; b++) out[(long)b * Vv + col] = acc[b];
}

// ---------------------------------------------------------------------------
extern "C" void kernel_launch(void* const* d_in, const int* in_sizes, int n_in,
                              void* d_out, int out_size)
{
    const int*   seq   = (const int*)  d_in[0];
    const float* embed = (const float*)d_in[1];
    const float* W1    = (const float*)d_in[2];
    const float* b1    = (const float*)d_in[3];
    const float* W2    = (const float*)d_in[4];
    const float* b2    = (const float*)d_in[5];
    const float* gamma = (const float*)d_in[6];
    const float* beta  = (const float*)d_in[7];
    const float* Wrp   = (const float*)d_in[8];
    const float* brp   = (const float*)d_in[9];
    const float* Wout  = (const float*)d_in[10];
    const float* bout  = (const float*)d_in[11];
    float* out = (float*)d_out;

    bf16 *W1h, *W1l, *W2h, *W2l, *t1h, *t1l, *Khg, *Klg;
    float *x, *he, *invn, *Tm, *mm;
    cudaGetSymbolAddress((void**)&W1h, g_W1h);
    cudaGetSymbolAddress((void**)&W1l, g_W1l);
    cudaGetSymbolAddress((void**)&W2h, g_W2h);
    cudaGetSymbolAddress((void**)&W2l, g_W2l);
    cudaGetSymbolAddress((void**)&t1h, g_t1h);
    cudaGetSymbolAddress((void**)&t1l, g_t1l);
    cudaGetSymbolAddress((void**)&Khg, g_Khg);
    cudaGetSymbolAddress((void**)&Klg, g_Klg);
    cudaGetSymbolAddress((void**)&x,    g_x);
    cudaGetSymbolAddress((void**)&he,   g_he);
    cudaGetSymbolAddress((void**)&invn, g_in);
    cudaGetSymbolAddress((void**)&Tm,   g_T);
    cudaGetSymbolAddress((void**)&mm,   g_mm);

    const int g1Smem = (2 * 2 * 64 * GSTR + 2 * 2 * 128 * GSTR) * 2;   // 61440
    const int g2Smem = (2 * 2 * 64 * GSTR + 2 * 2 * 64 * GSTR) * 2;    // 40960
    const int prepSmem = 2 * 64 * STRB * 2
                       + (64 * 65 + 64 * 65 + 32 * 33 + 64) * 4;
    const int scanSmem = (2 * 64 * KSTR + 2 * 64 * TSTR + 128
                          + 256 + 64 * 3 + 512) * 4;
    cudaFuncSetAttribute(gemm1_kernel,
        cudaFuncAttributeMaxDynamicSharedMemorySize, g1Smem);
    cudaFuncSetAttribute(gemm2_kernel,
        cudaFuncAttributeMaxDynamicSharedMemorySize, g2Smem);
    cudaFuncSetAttribute(prep_kernel,
        cudaFuncAttributeMaxDynamicSharedMemorySize, prepSmem);
    cudaFuncSetAttribute(scan_kernel,
        cudaFuncAttributeMaxDynamicSharedMemorySize, scanSmem);

    // 0a) W1 transpose/split   0b) W2 transpose/split
    convW_kernel<<<128, 256>>>(W1, W1h, W1l, Hd, 512, 16);
    convW_kernel<<<128, 256>>>(W2, W2h, W2l, 512, Hd, 8);

    // 1) t1 = relu(embed[seq] @ W1 + b1) -> bf16 hi/lo (fused gather)
    gemm1_kernel<<<dim3(512 / 128, NTOK / 64), 256, g1Smem>>>(
        W1h, W1l, b1, t1h, t1l, NTOK, 512, Hd, seq, embed);

    // 2) x = t1 @ W2 + b2 + embed[seq]   (profiled slot; 256 blocks now)
    gemm2_kernel<<<dim3(Hd / 64, NTOK / 64), 128, g2Smem>>>(
        t1h, t1l, W2h, W2l, b2, x, NTOK, Hd, 512, seq, embed);

    // 3) LN all rows: He, bf16 keys, invn
    ln_kernel<<<NTOK / 8, 256>>>(x, gamma, beta, he, Khg, Klg, invn);

    // 4) tensor-core Gram + chunk inverse T
    prep_kernel<<<Bq * NCH, 256, prepSmem>>>(Khg, Klg, invn, Tm);

    // 5) chunked backward scan -> mm (rp fused), 512 threads
    scan_kernel<<<Bq, 512, scanSmem>>>(he, invn, Tm, Wrp, brp, mm);

    // 6) out = mm @ Wout + bout
    out_kernel<<<Vv / 128, 128>>>(mm, Wout, bout, out);
}